// round 1
// baseline (speedup 1.0000x reference)
#include <cuda_runtime.h>

#define NN   200000
#define DIM  64
#define NV   (NN * DIM)
#define ALPHA 0.25f

// Scratch (device globals — no allocation allowed)
__device__ float g_x1[NV];
__device__ float g_x2[NV];
__device__ float g_x3[NV];
__device__ float g_out[NV];
__device__ float g_dis[NN];
__device__ int   g_deg[NN];

// Zero the layer buffers + degree counters
__global__ void k_init() {
    int i = blockIdx.x * blockDim.x + threadIdx.x;
    const int n4 = NV / 4;
    if (i < n4) {
        float4 z = make_float4(0.f, 0.f, 0.f, 0.f);
        ((float4*)g_x1)[i] = z;
        ((float4*)g_x2)[i] = z;
        ((float4*)g_x3)[i] = z;
    }
    if (i < NN) g_deg[i] = 0;
}

// In-degree via int atomics (deterministic)
__global__ void k_count(const int* __restrict__ col, int E) {
    int i = blockIdx.x * blockDim.x + threadIdx.x;
    if (i < E) atomicAdd(&g_deg[col[i]], 1);
}

// dis = deg^{-1/2}, 0 where deg==0
__global__ void k_dis() {
    int i = blockIdx.x * blockDim.x + threadIdx.x;
    if (i < NN) {
        int d = g_deg[i];
        g_dis[i] = (d > 0) ? rsqrtf((float)d) : 0.f;
    }
}

// One SpMM layer: xnew[c] += dis[r]*dis[c] * x[r], 16 lanes per edge,
// vector atomics (red.global.add.v4.f32) to cut atomic count 4x.
__global__ void k_scatter(const float* __restrict__ emb,
                          const int* __restrict__ row,
                          const int* __restrict__ col,
                          int E, int layer) {
    int t = blockIdx.x * blockDim.x + threadIdx.x;
    int e = t >> 4;
    int j = t & 15;
    if (e >= E) return;

    const float* x;
    float* xnew;
    if (layer == 0)      { x = emb;  xnew = g_x1; }
    else if (layer == 1) { x = g_x1; xnew = g_x2; }
    else                 { x = g_x2; xnew = g_x3; }

    int r = __ldg(row + e);
    int c = __ldg(col + e);
    float w = __ldg((const float*)g_dis + r) * __ldg((const float*)g_dis + c);

    float4 v = __ldg((const float4*)x + (size_t)r * 16 + j);
    float* dst = xnew + (size_t)c * 64 + j * 4;
    asm volatile("red.global.add.v4.f32 [%0], {%1, %2, %3, %4};"
                 :: "l"(dst), "f"(w * v.x), "f"(w * v.y), "f"(w * v.z), "f"(w * v.w)
                 : "memory");
}

// out = alpha * (emb + x1 + x2 + x3)
__global__ void k_combine(const float* __restrict__ emb) {
    int i = blockIdx.x * blockDim.x + threadIdx.x;
    const int n4 = NV / 4;
    if (i >= n4) return;
    float4 a = __ldg((const float4*)emb + i);
    float4 b = ((const float4*)g_x1)[i];
    float4 c = ((const float4*)g_x2)[i];
    float4 d = ((const float4*)g_x3)[i];
    float4 o;
    o.x = ALPHA * (a.x + b.x + c.x + d.x);
    o.y = ALPHA * (a.y + b.y + c.y + d.y);
    o.z = ALPHA * (a.z + b.z + c.z + d.z);
    o.w = ALPHA * (a.w + b.w + c.w + d.w);
    ((float4*)g_out)[i] = o;
}

// One warp per (user,item) pair: 64-dim dot product
__global__ void k_score(const int* __restrict__ batch, float* __restrict__ out, int P) {
    int t = blockIdx.x * blockDim.x + threadIdx.x;
    int p = t >> 5;
    int lane = t & 31;
    if (p >= P) return;

    int u = __ldg(batch + 3 * p);
    int v = __ldg(batch + 3 * p + 1);

    const float2* A = (const float2*)g_out + (size_t)u * 32;
    const float2* B = (const float2*)g_out + (size_t)v * 32;
    float2 a = __ldg(A + lane);
    float2 b = __ldg(B + lane);
    float s = a.x * b.x + a.y * b.y;

    #pragma unroll
    for (int o = 16; o; o >>= 1) s += __shfl_xor_sync(0xFFFFFFFFu, s, o);
    if (lane == 0) out[p] = s;
}

extern "C" void kernel_launch(void* const* d_in, const int* in_sizes, int n_in,
                              void* d_out, int out_size) {
    const float* emb   = (const float*)d_in[0];
    const int*   ei    = (const int*)d_in[1];
    const int*   batch = (const int*)d_in[2];
    float*       out   = (float*)d_out;

    int E = in_sizes[1] / 2;
    const int* row = ei;
    const int* col = ei + E;
    int P = in_sizes[2] / 3;

    k_init<<<(NV / 4 + 255) / 256, 256>>>();
    k_count<<<(E + 255) / 256, 256>>>(col, E);
    k_dis<<<(NN + 255) / 256, 256>>>();

    for (int layer = 0; layer < 3; layer++) {
        long long threads = (long long)E * 16;
        int blocks = (int)((threads + 255) / 256);
        k_scatter<<<blocks, 256>>>(emb, row, col, E, layer);
    }

    k_combine<<<(NV / 4 + 255) / 256, 256>>>(emb);

    long long sthreads = (long long)P * 32;
    k_score<<<(int)((sthreads + 255) / 256), 256>>>(batch, out, P);
}

// round 3
// speedup vs baseline: 1.4616x; 1.4616x over previous
#include <cuda_runtime.h>

#define NN   200000
#define DIM  64
#define NV   (NN * DIM)
#define EMAX 1250000
#define ALPHA 0.25f
#define NB_SCAN ((NN + 1023) / 1024)   // 196

// Scratch (device globals — no allocation allowed).
// NOTE: never pass these symbols from host code; select inside kernels.
__device__ float g_x1[NV];
__device__ float g_x2[NV];
__device__ float g_out[NV];
__device__ float g_dis[NN];
__device__ int   g_deg[NN];
__device__ int   g_off[NN];
__device__ int   g_cur[NN];
__device__ int   g_bsum[NB_SCAN];
__device__ int   g_bpre[NB_SCAN];
__device__ int   g_src[EMAX];
__device__ float g_wgt[EMAX];

// ---- degree / normalization ----
__global__ void k_deg0() {
    int i = blockIdx.x * blockDim.x + threadIdx.x;
    if (i < NN) { g_deg[i] = 0; g_cur[i] = 0; }
}

__global__ void k_count(const int* __restrict__ col, int E) {
    int i = blockIdx.x * blockDim.x + threadIdx.x;
    if (i < E) atomicAdd(&g_deg[col[i]], 1);
}

__global__ void k_dis() {
    int i = blockIdx.x * blockDim.x + threadIdx.x;
    if (i < NN) {
        int d = g_deg[i];
        g_dis[i] = (d > 0) ? rsqrtf((float)d) : 0.f;
    }
}

// ---- exclusive scan of degrees (3-kernel Hillis-Steele) ----
__global__ void k_scan1() {
    __shared__ int s[1024];
    int tid = threadIdx.x;
    int i = blockIdx.x * 1024 + tid;
    int v = (i < NN) ? g_deg[i] : 0;
    s[tid] = v;
    __syncthreads();
    #pragma unroll
    for (int o = 1; o < 1024; o <<= 1) {
        int t = (tid >= o) ? s[tid - o] : 0;
        __syncthreads();
        s[tid] += t;
        __syncthreads();
    }
    if (i < NN) g_off[i] = s[tid] - v;
    if (tid == 1023) g_bsum[blockIdx.x] = s[1023];
}

__global__ void k_scan2() {
    __shared__ int s[256];
    int tid = threadIdx.x;
    int v = (tid < NB_SCAN) ? g_bsum[tid] : 0;
    s[tid] = v;
    __syncthreads();
    #pragma unroll
    for (int o = 1; o < 256; o <<= 1) {
        int t = (tid >= o) ? s[tid - o] : 0;
        __syncthreads();
        s[tid] += t;
        __syncthreads();
    }
    if (tid < NB_SCAN) g_bpre[tid] = s[tid] - v;
}

__global__ void k_scan3() {
    int i = blockIdx.x * blockDim.x + threadIdx.x;
    if (i < NN) g_off[i] += g_bpre[i >> 10];
}

// ---- CSR fill: slot per (dst, edge) with precomputed weight ----
__global__ void k_fill(const int* __restrict__ row, const int* __restrict__ col, int E) {
    int e = blockIdx.x * blockDim.x + threadIdx.x;
    if (e >= E) return;
    int r = __ldg(row + e);
    int c = __ldg(col + e);
    int slot = g_off[c] + atomicAdd(&g_cur[c], 1);
    g_src[slot] = r;
    g_wgt[slot] = __ldg((const float*)g_dis + r) * __ldg((const float*)g_dis + c);
}

// ---- gather SpMM layers 0/1: xnew[c] = sum_k w_k * x[src_k]
// Buffer selection happens IN DEVICE CODE (device symbols are not valid
// host-side kernel arguments). 16 lanes per node.
__global__ void k_gather(const float* __restrict__ emb, int layer) {
    int t = blockIdx.x * blockDim.x + threadIdx.x;
    int node = t >> 4;
    int j = t & 15;
    if (node >= NN) return;

    const float* x  = (layer == 0) ? emb  : (const float*)g_x1;
    float*       xn = (layer == 0) ? g_x1 : g_x2;

    int beg = __ldg(g_off + node);
    int end = beg + __ldg(g_deg + node);
    float4 acc = make_float4(0.f, 0.f, 0.f, 0.f);
    for (int k = beg; k < end; k++) {
        int r = __ldg(g_src + k);
        float w = __ldg(g_wgt + k);
        float4 v = __ldg((const float4*)x + (size_t)r * 16 + j);
        acc.x += w * v.x; acc.y += w * v.y; acc.z += w * v.z; acc.w += w * v.w;
    }
    ((float4*)xn)[(size_t)node * 16 + j] = acc;
}

// ---- final layer fused with alpha-combine:
// out = 0.25*(emb + x1 + x2 + gather(x2)) ----
__global__ void k_gather_final(const float* __restrict__ emb) {
    int t = blockIdx.x * blockDim.x + threadIdx.x;
    int node = t >> 4;
    int j = t & 15;
    if (node >= NN) return;
    int beg = __ldg(g_off + node);
    int end = beg + __ldg(g_deg + node);
    float4 acc = make_float4(0.f, 0.f, 0.f, 0.f);
    for (int k = beg; k < end; k++) {
        int r = __ldg(g_src + k);
        float w = __ldg(g_wgt + k);
        float4 v = __ldg((const float4*)g_x2 + (size_t)r * 16 + j);
        acc.x += w * v.x; acc.y += w * v.y; acc.z += w * v.z; acc.w += w * v.w;
    }
    size_t idx = (size_t)node * 16 + j;
    float4 a = __ldg((const float4*)emb + idx);
    float4 b = ((const float4*)g_x1)[idx];
    float4 c = ((const float4*)g_x2)[idx];
    float4 o;
    o.x = ALPHA * (a.x + b.x + c.x + acc.x);
    o.y = ALPHA * (a.y + b.y + c.y + acc.y);
    o.z = ALPHA * (a.z + b.z + c.z + acc.z);
    o.w = ALPHA * (a.w + b.w + c.w + acc.w);
    ((float4*)g_out)[idx] = o;
}

// ---- scoring: one warp per (user,item) pair ----
__global__ void k_score(const int* __restrict__ batch, float* __restrict__ out, int P) {
    int t = blockIdx.x * blockDim.x + threadIdx.x;
    int p = t >> 5;
    int lane = t & 31;
    if (p >= P) return;
    int u = __ldg(batch + 3 * p);
    int v = __ldg(batch + 3 * p + 1);
    const float2* A = (const float2*)g_out + (size_t)u * 32;
    const float2* B = (const float2*)g_out + (size_t)v * 32;
    float2 a = __ldg(A + lane);
    float2 b = __ldg(B + lane);
    float s = a.x * b.x + a.y * b.y;
    #pragma unroll
    for (int o = 16; o; o >>= 1) s += __shfl_xor_sync(0xFFFFFFFFu, s, o);
    if (lane == 0) out[p] = s;
}

extern "C" void kernel_launch(void* const* d_in, const int* in_sizes, int n_in,
                              void* d_out, int out_size) {
    const float* emb   = (const float*)d_in[0];
    const int*   ei    = (const int*)d_in[1];
    const int*   batch = (const int*)d_in[2];
    float*       out   = (float*)d_out;

    int E = in_sizes[1] / 2;
    const int* row = ei;
    const int* col = ei + E;
    int P = in_sizes[2] / 3;

    k_deg0<<<(NN + 255) / 256, 256>>>();
    k_count<<<(E + 255) / 256, 256>>>(col, E);
    k_dis<<<(NN + 255) / 256, 256>>>();
    k_scan1<<<NB_SCAN, 1024>>>();
    k_scan2<<<1, 256>>>();
    k_scan3<<<(NN + 255) / 256, 256>>>();
    k_fill<<<(E + 255) / 256, 256>>>(row, col, E);

    int gthreads = NN * 16;
    int gblocks = (gthreads + 255) / 256;
    k_gather<<<gblocks, 256>>>(emb, 0);
    k_gather<<<gblocks, 256>>>(emb, 1);
    k_gather_final<<<gblocks, 256>>>(emb);

    long long sthreads = (long long)P * 32;
    k_score<<<(int)((sthreads + 255) / 256), 256>>>(batch, out, P);
}

// round 4
// speedup vs baseline: 1.5124x; 1.0347x over previous
#include <cuda_runtime.h>

#define NN   200000
#define DIM  64
#define NV   (NN * DIM)
#define EMAX 1250000
#define ALPHA 0.25f
#define NB_SCAN ((NN + 1023) / 1024)   // 196

// Scratch (device globals — no allocation allowed).
// NOTE: never pass these symbols from host code; select inside kernels.
__device__ float g_x1[NV];
__device__ float g_x2[NV];
__device__ float g_out[NV];
__device__ float g_dis[NN];
__device__ int   g_deg[NN];
__device__ int   g_off[NN];     // block-local exclusive prefix
__device__ int   g_cur[NN];
__device__ int   g_bsum[NB_SCAN];
__device__ int   g_bpre[NB_SCAN];
__device__ int   g_src[EMAX];
__device__ float g_wgt[EMAX];

// ---- degree / normalization ----
__global__ void k_deg0() {
    int i = blockIdx.x * blockDim.x + threadIdx.x;
    if (i < NN) { g_deg[i] = 0; g_cur[i] = 0; }
}

__global__ void k_count(const int* __restrict__ col, int E) {
    int i = blockIdx.x * blockDim.x + threadIdx.x;
    if (i < E) atomicAdd(&g_deg[col[i]], 1);
}

__global__ void k_dis() {
    int i = blockIdx.x * blockDim.x + threadIdx.x;
    if (i < NN) {
        int d = g_deg[i];
        g_dis[i] = (d > 0) ? rsqrtf((float)d) : 0.f;
    }
}

// ---- exclusive scan of degrees (block-local + block sums) ----
__global__ void k_scan1() {
    __shared__ int s[1024];
    int tid = threadIdx.x;
    int i = blockIdx.x * 1024 + tid;
    int v = (i < NN) ? g_deg[i] : 0;
    s[tid] = v;
    __syncthreads();
    #pragma unroll
    for (int o = 1; o < 1024; o <<= 1) {
        int t = (tid >= o) ? s[tid - o] : 0;
        __syncthreads();
        s[tid] += t;
        __syncthreads();
    }
    if (i < NN) g_off[i] = s[tid] - v;   // block-local exclusive
    if (tid == 1023) g_bsum[blockIdx.x] = s[1023];
}

__global__ void k_scan2() {
    __shared__ int s[256];
    int tid = threadIdx.x;
    int v = (tid < NB_SCAN) ? g_bsum[tid] : 0;
    s[tid] = v;
    __syncthreads();
    #pragma unroll
    for (int o = 1; o < 256; o <<= 1) {
        int t = (tid >= o) ? s[tid - o] : 0;
        __syncthreads();
        s[tid] += t;
        __syncthreads();
    }
    if (tid < NB_SCAN) g_bpre[tid] = s[tid] - v;
}

// Finalize offsets AND fill CSR in one pass over nodes is not possible
// (fill is edge-parallel), so: fold the block-prefix add into fill's slot math
// and also write the finalized offset back for the gather kernels.
__global__ void k_off_final() {
    int i = blockIdx.x * blockDim.x + threadIdx.x;
    if (i < NN) g_off[i] += g_bpre[i >> 10];
}

// ---- CSR fill: slot per (dst, edge) with precomputed weight ----
__global__ void k_fill(const int* __restrict__ row, const int* __restrict__ col, int E) {
    int e = blockIdx.x * blockDim.x + threadIdx.x;
    if (e >= E) return;
    int r = __ldg(row + e);
    int c = __ldg(col + e);
    int slot = __ldg(g_off + c) + atomicAdd(&g_cur[c], 1);
    g_src[slot] = r;
    g_wgt[slot] = __ldg((const float*)g_dis + r) * __ldg((const float*)g_dis + c);
}

// ---- gather SpMM, unroll-by-4 for MLP. 16 lanes per node, float4 each. ----
// layer 0: emb -> g_x1 ; layer 1: g_x1 -> g_x2
__global__ void k_gather(const float* __restrict__ emb, int layer) {
    int t = blockIdx.x * blockDim.x + threadIdx.x;
    int node = t >> 4;
    int j = t & 15;
    if (node >= NN) return;

    const float4* x  = (layer == 0) ? (const float4*)emb  : (const float4*)g_x1;
    float4*       xn = (layer == 0) ? (float4*)g_x1 : (float4*)g_x2;

    int beg = __ldg(g_off + node);
    int end = beg + __ldg(g_deg + node);
    float4 acc = make_float4(0.f, 0.f, 0.f, 0.f);

    int k = beg;
    for (; k + 4 <= end; k += 4) {
        int r0 = __ldg(g_src + k);
        int r1 = __ldg(g_src + k + 1);
        int r2 = __ldg(g_src + k + 2);
        int r3 = __ldg(g_src + k + 3);
        float w0 = __ldg(g_wgt + k);
        float w1 = __ldg(g_wgt + k + 1);
        float w2 = __ldg(g_wgt + k + 2);
        float w3 = __ldg(g_wgt + k + 3);
        float4 v0 = __ldg(x + (size_t)r0 * 16 + j);
        float4 v1 = __ldg(x + (size_t)r1 * 16 + j);
        float4 v2 = __ldg(x + (size_t)r2 * 16 + j);
        float4 v3 = __ldg(x + (size_t)r3 * 16 + j);
        acc.x += w0 * v0.x + w1 * v1.x + w2 * v2.x + w3 * v3.x;
        acc.y += w0 * v0.y + w1 * v1.y + w2 * v2.y + w3 * v3.y;
        acc.z += w0 * v0.z + w1 * v1.z + w2 * v2.z + w3 * v3.z;
        acc.w += w0 * v0.w + w1 * v1.w + w2 * v2.w + w3 * v3.w;
    }
    for (; k < end; k++) {
        int r = __ldg(g_src + k);
        float w = __ldg(g_wgt + k);
        float4 v = __ldg(x + (size_t)r * 16 + j);
        acc.x += w * v.x; acc.y += w * v.y; acc.z += w * v.z; acc.w += w * v.w;
    }
    xn[(size_t)node * 16 + j] = acc;
}

// ---- final layer fused with alpha-combine: out = 0.25*(emb+x1+x2+gather(x2))
__global__ void k_gather_final(const float* __restrict__ emb) {
    int t = blockIdx.x * blockDim.x + threadIdx.x;
    int node = t >> 4;
    int j = t & 15;
    if (node >= NN) return;

    const float4* x = (const float4*)g_x2;
    int beg = __ldg(g_off + node);
    int end = beg + __ldg(g_deg + node);
    float4 acc = make_float4(0.f, 0.f, 0.f, 0.f);

    int k = beg;
    for (; k + 4 <= end; k += 4) {
        int r0 = __ldg(g_src + k);
        int r1 = __ldg(g_src + k + 1);
        int r2 = __ldg(g_src + k + 2);
        int r3 = __ldg(g_src + k + 3);
        float w0 = __ldg(g_wgt + k);
        float w1 = __ldg(g_wgt + k + 1);
        float w2 = __ldg(g_wgt + k + 2);
        float w3 = __ldg(g_wgt + k + 3);
        float4 v0 = __ldg(x + (size_t)r0 * 16 + j);
        float4 v1 = __ldg(x + (size_t)r1 * 16 + j);
        float4 v2 = __ldg(x + (size_t)r2 * 16 + j);
        float4 v3 = __ldg(x + (size_t)r3 * 16 + j);
        acc.x += w0 * v0.x + w1 * v1.x + w2 * v2.x + w3 * v3.x;
        acc.y += w0 * v0.y + w1 * v1.y + w2 * v2.y + w3 * v3.y;
        acc.z += w0 * v0.z + w1 * v1.z + w2 * v2.z + w3 * v3.z;
        acc.w += w0 * v0.w + w1 * v1.w + w2 * v2.w + w3 * v3.w;
    }
    for (; k < end; k++) {
        int r = __ldg(g_src + k);
        float w = __ldg(g_wgt + k);
        float4 v = __ldg(x + (size_t)r * 16 + j);
        acc.x += w * v.x; acc.y += w * v.y; acc.z += w * v.z; acc.w += w * v.w;
    }

    size_t idx = (size_t)node * 16 + j;
    float4 a = __ldg((const float4*)emb + idx);
    float4 b = ((const float4*)g_x1)[idx];
    float4 c = ((const float4*)g_x2)[idx];
    float4 o;
    o.x = ALPHA * (a.x + b.x + c.x + acc.x);
    o.y = ALPHA * (a.y + b.y + c.y + acc.y);
    o.z = ALPHA * (a.z + b.z + c.z + acc.z);
    o.w = ALPHA * (a.w + b.w + c.w + acc.w);
    ((float4*)g_out)[idx] = o;
}

// ---- scoring: 16 lanes per (user,item) pair, float4 loads ----
__global__ void k_score(const int* __restrict__ batch, float* __restrict__ out, int P) {
    int t = blockIdx.x * blockDim.x + threadIdx.x;
    int p = t >> 4;
    int lane = t & 15;
    if (p >= P) return;
    int u = __ldg(batch + 3 * p);
    int v = __ldg(batch + 3 * p + 1);
    float4 a = __ldg((const float4*)g_out + (size_t)u * 16 + lane);
    float4 b = __ldg((const float4*)g_out + (size_t)v * 16 + lane);
    float s = a.x * b.x + a.y * b.y + a.z * b.z + a.w * b.w;
    #pragma unroll
    for (int o = 8; o; o >>= 1) s += __shfl_xor_sync(0xFFFFFFFFu, s, o);
    if (lane == 0) out[p] = s;
}

extern "C" void kernel_launch(void* const* d_in, const int* in_sizes, int n_in,
                              void* d_out, int out_size) {
    const float* emb   = (const float*)d_in[0];
    const int*   ei    = (const int*)d_in[1];
    const int*   batch = (const int*)d_in[2];
    float*       out   = (float*)d_out;

    int E = in_sizes[1] / 2;
    const int* row = ei;
    const int* col = ei + E;
    int P = in_sizes[2] / 3;

    k_deg0<<<(NN + 255) / 256, 256>>>();
    k_count<<<(E + 255) / 256, 256>>>(col, E);
    k_dis<<<(NN + 255) / 256, 256>>>();
    k_scan1<<<NB_SCAN, 1024>>>();
    k_scan2<<<1, 256>>>();
    k_off_final<<<(NN + 255) / 256, 256>>>();
    k_fill<<<(E + 255) / 256, 256>>>(row, col, E);

    int gthreads = NN * 16;
    int gblocks = (gthreads + 255) / 256;
    k_gather<<<gblocks, 256>>>(emb, 0);
    k_gather<<<gblocks, 256>>>(emb, 1);
    k_gather_final<<<gblocks, 256>>>(emb);

    long long sthreads = (long long)P * 16;
    k_score<<<(int)((sthreads + 255) / 256), 256>>>(batch, out, P);
}